// round 3
// baseline (speedup 1.0000x reference)
#include <cuda_runtime.h>
#include <cstdio>

#define B_ 2
#define S_ 2048
#define D_ 1024
#define H_ 16
#define HD_ 64

// ---------------- scratch (device globals; no allocation allowed) ----------------
__device__ float g_q[(size_t)B_ * H_ * S_ * HD_];     // [B,H,S,Hd]
__device__ float g_kT[(size_t)B_ * H_ * HD_ * S_];    // [B,H,Hd,S]
__device__ float g_v[(size_t)B_ * H_ * S_ * HD_];     // [B,H,S,Hd]
__device__ float g_attn[(size_t)B_ * S_ * D_];        // [B,S,D] (H,Hd interleaved)
__device__ float g_scores[(size_t)B_ * H_ * S_ * S_]; // fallback weights buffer

// ---------------- epilogues ----------------
struct EpiQKV {
    const float* bias;
    __device__ __forceinline__ void operator()(int, int m, int n, float v) const {
        v += bias[n];
        int part = n >> 10;           // 0=q 1=k 2=v
        int rem = n & 1023;
        int h = rem >> 6;
        int d = rem & 63;
        int b = m >> 11;
        int s = m & 2047;
        size_t bh = (size_t)(b * H_ + h);
        if (part == 0)
            g_q[(bh * S_ + s) * HD_ + d] = v;
        else if (part == 1)
            g_kT[(bh * HD_ + d) * S_ + s] = v;
        else
            g_v[(bh * S_ + s) * HD_ + d] = v;
    }
};

struct EpiScore {
    float* dst; // [B*H, S, S]
    __device__ __forceinline__ void operator()(int bz, int m, int n, float v) const {
        dst[((size_t)bz * S_ + m) * S_ + n] = v * 0.125f; // 1/sqrt(64)
    }
};

struct EpiAV {
    __device__ __forceinline__ void operator()(int bz, int m, int n, float v) const {
        int b = bz >> 4;
        int h = bz & 15;
        g_attn[(((size_t)b * S_ + m) * H_ + h) * HD_ + n] = v;
    }
};

struct EpiOut {
    const float* bias;
    float* out;
    __device__ __forceinline__ void operator()(int, int m, int n, float v) const {
        out[(size_t)m * D_ + n] = v + bias[n];
    }
};

// ---------------- generic register-tiled fp32 SGEMM ----------------
// C[M,N] = A[M,K] (lda) @ B[K,N] (ldb), batched over blockIdx.z with strides.
template <int BM, int BN, int BK, int TM, int TN, class Epi>
__global__ void __launch_bounds__((BM / TM) * (BN / TN))
sgemm_kernel(const float* __restrict__ Aall, const float* __restrict__ Ball,
             int M, int N, int K, int lda, int ldb,
             long long strideA, long long strideB, Epi epi) {
    constexpr int NT = (BM / TM) * (BN / TN);
    const int bz = blockIdx.z;
    const float* A = Aall + (size_t)bz * strideA;
    const float* Bp = Ball + (size_t)bz * strideB;

    __shared__ float As[BK][BM];
    __shared__ float Bs[BK][BN];

    const int tid = threadIdx.x;
    const int tx = tid % (BN / TN);
    const int ty = tid / (BN / TN);
    const int row0 = blockIdx.y * BM;
    const int col0 = blockIdx.x * BN;

    float acc[TM][TN];
#pragma unroll
    for (int i = 0; i < TM; i++)
#pragma unroll
        for (int j = 0; j < TN; j++) acc[i][j] = 0.f;

    constexpr int AV = (BM * BK / 4) / NT; // float4 loads per thread for A
    constexpr int BV = (BK * BN / 4) / NT; // float4 loads per thread for B
    static_assert(AV * NT == BM * BK / 4, "A tile divisibility");
    static_assert(BV * NT == BK * BN / 4, "B tile divisibility");
    static_assert(TM % 4 == 0 && TN % 4 == 0, "vector frag reads");

    for (int k0 = 0; k0 < K; k0 += BK) {
#pragma unroll
        for (int it = 0; it < AV; ++it) {
            int i = tid + it * NT;
            int r = i / (BK / 4);
            int c4 = (i % (BK / 4)) * 4;
            float4 v = *reinterpret_cast<const float4*>(
                &A[(size_t)(row0 + r) * lda + k0 + c4]);
            As[c4 + 0][r] = v.x;
            As[c4 + 1][r] = v.y;
            As[c4 + 2][r] = v.z;
            As[c4 + 3][r] = v.w;
        }
#pragma unroll
        for (int it = 0; it < BV; ++it) {
            int i = tid + it * NT;
            int r = i / (BN / 4);
            int c4 = (i % (BN / 4)) * 4;
            *reinterpret_cast<float4*>(&Bs[r][c4]) =
                *reinterpret_cast<const float4*>(
                    &Bp[(size_t)(k0 + r) * ldb + col0 + c4]);
        }
        __syncthreads();

#pragma unroll
        for (int kk = 0; kk < BK; kk++) {
            float ra[TM], rb[TN];
#pragma unroll
            for (int i = 0; i < TM / 4; i++)
                *reinterpret_cast<float4*>(&ra[i * 4]) =
                    *reinterpret_cast<const float4*>(&As[kk][ty * TM + i * 4]);
#pragma unroll
            for (int j = 0; j < TN / 4; j++)
                *reinterpret_cast<float4*>(&rb[j * 4]) =
                    *reinterpret_cast<const float4*>(&Bs[kk][tx * TN + j * 4]);
#pragma unroll
            for (int i = 0; i < TM; i++)
#pragma unroll
                for (int j = 0; j < TN; j++)
                    acc[i][j] = fmaf(ra[i], rb[j], acc[i][j]);
        }
        __syncthreads();
    }

#pragma unroll
    for (int i = 0; i < TM; i++)
#pragma unroll
        for (int j = 0; j < TN; j++)
            epi(bz, row0 + ty * TM + i, col0 + tx * TN + j, acc[i][j]);
}

// ---------------- softmax: one block per row, IN-PLACE ----------------
__global__ void __launch_bounds__(256)
softmax_kernel(float* __restrict__ buf) {
    const size_t row = blockIdx.x;
    float* d = buf + row * S_;
    const int tid = threadIdx.x;

    float4 a = *reinterpret_cast<const float4*>(d + tid * 4);
    float4 b = *reinterpret_cast<const float4*>(d + 1024 + tid * 4);

    float m = fmaxf(fmaxf(fmaxf(a.x, a.y), fmaxf(a.z, a.w)),
                    fmaxf(fmaxf(b.x, b.y), fmaxf(b.z, b.w)));
#pragma unroll
    for (int o = 16; o; o >>= 1) m = fmaxf(m, __shfl_xor_sync(0xffffffffu, m, o));

    __shared__ float redm[8];
    if ((tid & 31) == 0) redm[tid >> 5] = m;
    __syncthreads();
    m = redm[0];
#pragma unroll
    for (int w = 1; w < 8; w++) m = fmaxf(m, redm[w]);

    a.x = __expf(a.x - m); a.y = __expf(a.y - m);
    a.z = __expf(a.z - m); a.w = __expf(a.w - m);
    b.x = __expf(b.x - m); b.y = __expf(b.y - m);
    b.z = __expf(b.z - m); b.w = __expf(b.w - m);

    float sum = (a.x + a.y) + (a.z + a.w) + (b.x + b.y) + (b.z + b.w);
#pragma unroll
    for (int o = 16; o; o >>= 1) sum += __shfl_xor_sync(0xffffffffu, sum, o);

    __shared__ float reds[8];
    if ((tid & 31) == 0) reds[tid >> 5] = sum;
    __syncthreads();
    sum = reds[0];
#pragma unroll
    for (int w = 1; w < 8; w++) sum += reds[w];

    float inv = 1.0f / sum;
    a.x *= inv; a.y *= inv; a.z *= inv; a.w *= inv;
    b.x *= inv; b.y *= inv; b.z *= inv; b.w *= inv;

    *reinterpret_cast<float4*>(d + tid * 4) = a;
    *reinterpret_cast<float4*>(d + 1024 + tid * 4) = b;
}

// ---------------- launch ----------------
extern "C" void kernel_launch(void* const* d_in, const int* in_sizes, int n_in,
                              void* d_out, int out_size) {
    const float* query = (const float*)d_in[0]; // [B,S,D]
    const float* W_qkv = (const float*)d_in[1]; // [D,3D]
    const float* b_qkv = (const float*)d_in[2]; // [3D]
    const float* W_out = (const float*)d_in[3]; // [D,D]
    const float* b_out = (const float*)d_in[4]; // [D]
    float* out = (float*)d_out;

    const size_t OUT_ELEMS = (size_t)B_ * S_ * D_;      // 4,194,304
    const size_t ATT_ELEMS = (size_t)B_ * H_ * S_ * S_; // 134,217,728

    float* scores_ptr = nullptr;
    cudaGetSymbolAddress((void**)&scores_ptr, g_scores);

    // weights destination: second chunk of d_out if present, else scratch
    float* wdst = ((size_t)out_size >= OUT_ELEMS + ATT_ELEMS) ? (out + OUT_ELEMS)
                                                              : scores_ptr;

    float *qp, *kp, *vp, *ap;
    cudaGetSymbolAddress((void**)&qp, g_q);
    cudaGetSymbolAddress((void**)&kp, g_kT);
    cudaGetSymbolAddress((void**)&vp, g_v);
    cudaGetSymbolAddress((void**)&ap, g_attn);

    // 1) QKV: [4096,1024] @ [1024,3072], scatter into q / kT / v
    {
        dim3 grid(3 * D_ / 128, (B_ * S_) / 128, 1);
        EpiQKV epi{b_qkv};
        sgemm_kernel<128, 128, 16, 8, 8, EpiQKV><<<grid, 256>>>(
            query, W_qkv, B_ * S_, 3 * D_, D_, D_, 3 * D_, 0LL, 0LL, epi);
    }

    // 2) scores: per (b,h) [2048,64] @ [64,2048] -> wdst directly (scaled)
    {
        dim3 grid(S_ / 128, S_ / 128, B_ * H_);
        EpiScore epi{wdst};
        sgemm_kernel<128, 128, 16, 8, 8, EpiScore><<<grid, 256>>>(
            qp, kp, S_, S_, HD_, HD_, S_,
            (long long)S_ * HD_, (long long)HD_ * S_, epi);
    }

    // 3) softmax rows, in place on wdst
    {
        softmax_kernel<<<B_ * H_ * S_, 256>>>(wdst);
    }

    // 4) AV: per (b,h) [2048,2048] @ [2048,64] -> g_attn (B,S,H,Hd layout)
    {
        dim3 grid(HD_ / 64, S_ / 128, B_ * H_);
        EpiAV epi{};
        sgemm_kernel<128, 64, 16, 8, 4, EpiAV><<<grid, 256>>>(
            wdst, vp, S_, HD_, S_, S_, HD_,
            (long long)S_ * S_, (long long)S_ * HD_, epi);
    }

    // 5) out proj: [4096,1024] @ [1024,1024] + b -> d_out head
    {
        dim3 grid(D_ / 128, (B_ * S_) / 128, 1);
        EpiOut epi{b_out, out};
        sgemm_kernel<128, 128, 16, 8, 8, EpiOut><<<grid, 256>>>(
            ap, W_out, B_ * S_, D_, D_, D_, D_, 0LL, 0LL, epi);
    }
}